// round 8
// baseline (speedup 1.0000x reference)
#include <cuda_runtime.h>
#include <cuda_bf16.h>
#include <cstdint>

#define BIGV 10000000000.0f
#define F_L2E 1.4426950408889634f
#define F_LN2 0.6931471805599453f

// D (pre-scaled by log2(e)) in 4x4-tile-major layout:
// g_D4[(((b*128 + t)*128 + c)*16) + k*4 + m] = log2e * D[b][4t+k][4c+m]
// (t = row-block 0..127, c = col-block 0..127, k,m in 0..3). 67 MB.
__device__ float g_D4[(size_t)64 * 128 * 128 * 16];

__device__ __forceinline__ float ex2f_(float x) {
    float r; asm("ex2.approx.f32 %0, %1;" : "=f"(r) : "f"(x)); return r;
}
__device__ __forceinline__ float lg2f_(float x) {
    float r; asm("lg2.approx.f32 %0, %1;" : "=f"(r) : "f"(x)); return r;
}
__device__ __forceinline__ void st_release_shared(int* p, int v) {
    unsigned a = (unsigned)__cvta_generic_to_shared(p);
    asm volatile("st.release.cta.shared.b32 [%0], %1;" :: "r"(a), "r"(v) : "memory");
}
__device__ __forceinline__ int ld_acquire_shared(const int* p) {
    unsigned a = (unsigned)__cvta_generic_to_shared(p);
    int v; asm volatile("ld.acquire.cta.shared.b32 %0, [%1];" : "=r"(v) : "r"(a) : "memory");
    return v;
}

// softmin in log2 domain: mn - lg2(1 + 2^(mn-mid) + 2^(mn-mx)), order-free args.
__device__ __forceinline__ float smin3(float a, float b, float c) {
    float lo = fminf(a, c), hi = fmaxf(a, c);
    float mn  = fminf(lo, b);
    float mid = fminf(fmaxf(lo, b), hi);
    float mx  = fmaxf(hi, b);
    float t = ex2f_(mn - mid) + ex2f_(mn - mx);
    return mn - lg2f_(1.0f + t);
}

// ---------------------------------------------------------------------------
// Kernel 1: squared distances * log2e, written 4x4-tile-major.
// Grid (8, 8, 64): one 64x64 (i,j) tile per block, 256 threads, 4x4 microtile.
// ---------------------------------------------------------------------------
__global__ __launch_bounds__(256) void sqdist_kernel(const float* __restrict__ x,
                                                     const float* __restrict__ y)
{
    __shared__ __align__(16) float xs[16][64];
    __shared__ __align__(16) float ys[16][64];
    __shared__ float x2s[64], y2s[64];
    __shared__ __align__(16) float ts[64][68];   // stride 68 (16B-multiple)

    const int b   = blockIdx.z;
    const int i0  = blockIdx.y * 64;
    const int j0  = blockIdx.x * 64;
    const int tid = threadIdx.x;

    {
        int row = tid >> 2;
        int d0  = (tid & 3) * 4;
        float4 xv = *(const float4*)(x + ((size_t)(b * 512 + i0 + row)) * 16 + d0);
        xs[d0 + 0][row] = xv.x; xs[d0 + 1][row] = xv.y;
        xs[d0 + 2][row] = xv.z; xs[d0 + 3][row] = xv.w;
        float4 yv = *(const float4*)(y + ((size_t)(b * 512 + j0 + row)) * 16 + d0);
        ys[d0 + 0][row] = yv.x; ys[d0 + 1][row] = yv.y;
        ys[d0 + 2][row] = yv.z; ys[d0 + 3][row] = yv.w;
    }
    __syncthreads();

    if (tid < 64) {
        float s = 0.f;
        #pragma unroll
        for (int d = 0; d < 16; d++) s += xs[d][tid] * xs[d][tid];
        x2s[tid] = s;
    } else if (tid < 128) {
        int c = tid - 64;
        float s = 0.f;
        #pragma unroll
        for (int d = 0; d < 16; d++) s += ys[d][c] * ys[d][c];
        y2s[c] = s;
    }
    __syncthreads();

    const int tx = tid & 15;
    const int ty = tid >> 4;
    float acc[4][4];
    #pragma unroll
    for (int r = 0; r < 4; r++)
        #pragma unroll
        for (int c = 0; c < 4; c++) acc[r][c] = 0.f;

    #pragma unroll
    for (int d = 0; d < 16; d++) {
        float4 av = *(const float4*)&xs[d][ty * 4];
        float4 bv = *(const float4*)&ys[d][tx * 4];
        float a[4]  = {av.x, av.y, av.z, av.w};
        float bb[4] = {bv.x, bv.y, bv.z, bv.w};
        #pragma unroll
        for (int r = 0; r < 4; r++)
            #pragma unroll
            for (int c = 0; c < 4; c++) acc[r][c] = fmaf(a[r], bb[c], acc[r][c]);
    }

    #pragma unroll
    for (int r = 0; r < 4; r++) {
        float xv2 = x2s[ty * 4 + r];
        #pragma unroll
        for (int c = 0; c < 4; c++)
            ts[ty * 4 + r][tx * 4 + c] =
                fmaf(-2.f, acc[r][c], xv2 + y2s[tx * 4 + c]) * F_L2E;
    }
    __syncthreads();

    // Store to tile-major: idx over (ii, cb_local): 64 x 16 float4 groups.
    #pragma unroll
    for (int rep = 0; rep < 4; ++rep) {
        int idx = tid + rep * 256;           // 0..1023
        int ii  = idx >> 4;                  // 0..63
        int cbl = idx & 15;                  // 0..15
        int r   = i0 + ii;
        size_t dst = (((size_t)b * 128 + (r >> 2)) * 128 + ((j0 >> 2) + cbl)) * 4
                     + (r & 3);              // in float4 units
        ((float4*)g_D4)[dst] = *(const float4*)&ts[ii][cbl * 4];
    }
}

// ---------------------------------------------------------------------------
// Kernel 2: soft-DTW wavefront, 4x4 register tile per thread per iteration.
// 64 blocks x 128 threads = 4 warps; thread t = 32w+l owns rows 4t+1..4t+4
// (1-based). Iteration n: lane l computes tile-col c = n - l (cols 4c+1..4c+4).
// Carried: prevL[0..3] (right col), bot[0..3] (bottom row, shfl'd to lane+1),
// tdiag (up-left corner). Cross-warp: lane31 bottom row -> ringC[w+1][c]
// (float4) + prog (release/acquire, warp-uniform spin). ring[0] prefilled BIG.
// Values carry an implicit log2(e) factor (D pre-scaled).
// ---------------------------------------------------------------------------
__global__ __launch_bounds__(128) void dtw_kernel(float* __restrict__ out)
{
    __shared__ __align__(16) float4 ringC[4][128];
    __shared__ int prog[4];

    const int b    = blockIdx.x;
    const int tid  = threadIdx.x;
    const int lane = tid & 31;
    const int w    = tid >> 5;
    const bool lane0 = (lane == 0);

    ringC[0][tid & 127] = make_float4(BIGV, BIGV, BIGV, BIGV);
    if (tid < 4) prog[tid] = 0;
    __syncthreads();

    const float4* __restrict__ Dp =
        (const float4*)g_D4 + (size_t)(b * 128 + tid) * 128 * 4;

    float prevL0 = BIGV, prevL1 = BIGV, prevL2 = BIGV, prevL3 = BIGV;
    float bot0 = BIGV, bot1 = BIGV, bot2 = BIGV, bot3 = BIGV;
    float tdiag = (w == 0 && lane0) ? 0.0f : BIGV;
    int pcache = 0;

    float4 cur0 = Dp[0], cur1 = Dp[1], cur2 = Dp[2], cur3 = Dp[3];

    #pragma unroll 1
    for (int n = 0; n < 159; ++n) {
        const int c = n - lane;

        // Prefetch next tile (clamped).
        int cl = c + 1; cl = cl < 0 ? 0 : (cl > 127 ? 127 : cl);
        float4 nx0 = Dp[cl * 4 + 0], nx1 = Dp[cl * 4 + 1];
        float4 nx2 = Dp[cl * 4 + 2], nx3 = Dp[cl * 4 + 3];

        // Neighbor bottom row from previous iteration.
        float s0 = __shfl_up_sync(0xffffffffu, bot0, 1);
        float s1 = __shfl_up_sync(0xffffffffu, bot1, 1);
        float s2 = __shfl_up_sync(0xffffffffu, bot2, 1);
        float s3 = __shfl_up_sync(0xffffffffu, bot3, 1);

        // Warp-uniform wait for producer warp's tile-col n, then broadcast read.
        if (w > 0 && n < 128 && pcache < n + 1) {
            int p = ld_acquire_shared(&prog[w]);
            while (p < n + 1) { __nanosleep(32); p = ld_acquire_shared(&prog[w]); }
            pcache = p;
        }
        float4 rv = ringC[w][n < 128 ? n : 127];

        float t0 = lane0 ? rv.x : s0;
        float t1 = lane0 ? rv.y : s1;
        float t2 = lane0 ? rv.z : s2;
        float t3 = lane0 ? rv.w : s3;
        float dg = tdiag;
        tdiag = t3;

        // 4x4 tile DP.
        float v00 = smin3(dg,     t0,  prevL0) + cur0.x;
        float v01 = smin3(t0,     t1,  v00)    + cur0.y;
        float v02 = smin3(t1,     t2,  v01)    + cur0.z;
        float v03 = smin3(t2,     t3,  v02)    + cur0.w;
        float v10 = smin3(prevL0, v00, prevL1) + cur1.x;
        float v11 = smin3(v00,    v01, v10)    + cur1.y;
        float v12 = smin3(v01,    v02, v11)    + cur1.z;
        float v13 = smin3(v02,    v03, v12)    + cur1.w;
        float v20 = smin3(prevL1, v10, prevL2) + cur2.x;
        float v21 = smin3(v10,    v11, v20)    + cur2.y;
        float v22 = smin3(v11,    v12, v21)    + cur2.z;
        float v23 = smin3(v12,    v13, v22)    + cur2.w;
        float v30 = smin3(prevL2, v20, prevL3) + cur3.x;
        float v31 = smin3(v20,    v21, v30)    + cur3.y;
        float v32 = smin3(v21,    v22, v31)    + cur3.z;
        float v33 = smin3(v22,    v23, v32)    + cur3.w;

        const bool act = ((unsigned)c < 128u);
        prevL0 = act ? v03 : prevL0;
        prevL1 = act ? v13 : prevL1;
        prevL2 = act ? v23 : prevL2;
        prevL3 = act ? v33 : prevL3;
        bot0 = act ? v30 : bot0;
        bot1 = act ? v31 : bot1;
        bot2 = act ? v32 : bot2;
        bot3 = act ? v33 : bot3;

        if (lane == 31 && act && w < 3) {
            ringC[w + 1][c] = make_float4(v30, v31, v32, v33);
            st_release_shared(&prog[w + 1], c + 1);
        }
        if (tid == 127 && c == 127) out[b] = v33 * F_LN2;   // R[512][512]

        cur0 = nx0; cur1 = nx1; cur2 = nx2; cur3 = nx3;
    }
}

extern "C" void kernel_launch(void* const* d_in, const int* in_sizes, int n_in,
                              void* d_out, int out_size)
{
    const float* x = (const float*)d_in[0];
    const float* y = (const float*)d_in[1];
    float* out = (float*)d_out;

    dim3 g1(8, 8, 64);
    sqdist_kernel<<<g1, 256>>>(x, y);
    dtw_kernel<<<64, 128>>>(out);
}